// round 2
// baseline (speedup 1.0000x reference)
#include <cuda_runtime.h>
#include <math.h>

#define B_DIM 4096
#define D_DIM 1024
#define TEMP_INV 20.0f   // 1 / 0.05

// Scratch (no allocations allowed)
__device__ float g_tnorm2[B_DIM];
__device__ float g_mnorm2[B_DIM];
__device__ float g_diaglogit[B_DIM];   // -d_ii / T
__device__ float g_rowsum[B_DIM];      // sum_{j!=i} exp(l_ij - l_ii)

// ---------------------------------------------------------------------------
// Kernel A: per-row ||t||^2, ||m||^2, t.m (diag), zero rowsum.
// One block per row, 256 threads, each handles one float4 of the 1024-dim row.
// ---------------------------------------------------------------------------
__global__ void __launch_bounds__(256) row_stats_kernel(const float* __restrict__ t,
                                                        const float* __restrict__ m) {
    int row = blockIdx.x;
    const float4* tr = reinterpret_cast<const float4*>(t + (size_t)row * D_DIM);
    const float4* mr = reinterpret_cast<const float4*>(m + (size_t)row * D_DIM);

    float4 a = tr[threadIdx.x];
    float4 b = mr[threadIdx.x];
    float st = a.x * a.x + a.y * a.y + a.z * a.z + a.w * a.w;
    float sm = b.x * b.x + b.y * b.y + b.z * b.z + b.w * b.w;
    float sd = a.x * b.x + a.y * b.y + a.z * b.z + a.w * b.w;

    // warp reduce
    #pragma unroll
    for (int off = 16; off > 0; off >>= 1) {
        st += __shfl_xor_sync(0xffffffffu, st, off);
        sm += __shfl_xor_sync(0xffffffffu, sm, off);
        sd += __shfl_xor_sync(0xffffffffu, sd, off);
    }
    __shared__ float red[3][8];
    int wid = threadIdx.x >> 5;
    int lid = threadIdx.x & 31;
    if (lid == 0) { red[0][wid] = st; red[1][wid] = sm; red[2][wid] = sd; }
    __syncthreads();
    if (threadIdx.x == 0) {
        float a0 = 0.f, a1 = 0.f, a2 = 0.f;
        #pragma unroll
        for (int w = 0; w < 8; w++) { a0 += red[0][w]; a1 += red[1][w]; a2 += red[2][w]; }
        g_tnorm2[row] = a0;
        g_mnorm2[row] = a1;
        float d2 = a0 + a1 - 2.0f * a2;
        g_diaglogit[row] = -sqrtf(fmaxf(d2, 0.0f)) * TEMP_INV;
        g_rowsum[row] = 0.0f;
    }
}

// ---------------------------------------------------------------------------
// Kernel B: fused SGEMM + distance/exp epilogue.
// Tile 128x128, BK=8, 256 threads, 8x8 micro-tile per thread.
// ---------------------------------------------------------------------------
#define BM 128
#define BN 128
#define BK 8
#define TM 8
#define TN 8

__global__ void __launch_bounds__(256) gemm_lse_kernel(const float* __restrict__ T,
                                                       const float* __restrict__ M) {
    __shared__ float As[BK][BM];
    __shared__ float Bs[BK][BN];

    const int tid = threadIdx.x;
    const int tx = tid & 15;        // 0..15 -> column groups of 8
    const int ty = tid >> 4;        // 0..15 -> row groups of 8
    const int rowBase = blockIdx.y * BM;
    const int colBase = blockIdx.x * BN;

    // load mapping: 256 threads, each loads one float4 of A and one of B per k-step
    const int lr = tid >> 1;          // 0..127 : tile row
    const int lc = (tid & 1) * 4;     // 0 or 4 : k offset
    const float* Tp = T + (size_t)(rowBase + lr) * D_DIM + lc;
    const float* Mp = M + (size_t)(colBase + lr) * D_DIM + lc;

    float acc[TM][TN];
    #pragma unroll
    for (int i = 0; i < TM; i++)
        #pragma unroll
        for (int j = 0; j < TN; j++) acc[i][j] = 0.0f;

    for (int k0 = 0; k0 < D_DIM; k0 += BK) {
        float4 av = *reinterpret_cast<const float4*>(Tp + k0);
        float4 bv = *reinterpret_cast<const float4*>(Mp + k0);
        __syncthreads();
        As[lc + 0][lr] = av.x; As[lc + 1][lr] = av.y;
        As[lc + 2][lr] = av.z; As[lc + 3][lr] = av.w;
        Bs[lc + 0][lr] = bv.x; Bs[lc + 1][lr] = bv.y;
        Bs[lc + 2][lr] = bv.z; Bs[lc + 3][lr] = bv.w;
        __syncthreads();

        #pragma unroll
        for (int kk = 0; kk < BK; kk++) {
            float a[TM], b[TN];
            #pragma unroll
            for (int i = 0; i < TM; i++) a[i] = As[kk][ty * TM + i];
            #pragma unroll
            for (int j = 0; j < TN; j++) b[j] = Bs[kk][tx * TN + j];
            #pragma unroll
            for (int i = 0; i < TM; i++)
                #pragma unroll
                for (int j = 0; j < TN; j++) acc[i][j] = fmaf(a[i], b[j], acc[i][j]);
        }
    }

    // Epilogue: d2 = |t|^2 + |m|^2 - 2 t.m ; logit = -sqrt(d2)/T ;
    // accumulate exp(logit - diaglogit) excluding j == i.
    float mn[TN];
    #pragma unroll
    for (int j = 0; j < TN; j++) mn[j] = g_mnorm2[colBase + tx * TN + j];

    #pragma unroll
    for (int i = 0; i < TM; i++) {
        int gi = rowBase + ty * TM + i;
        float tn = g_tnorm2[gi];
        float dl = g_diaglogit[gi];
        float psum = 0.0f;
        #pragma unroll
        for (int j = 0; j < TN; j++) {
            int gj = colBase + tx * TN + j;
            float d2 = tn + mn[j] - 2.0f * acc[i][j];
            float l = -sqrtf(fmaxf(d2, 0.0f)) * TEMP_INV;
            float e = __expf(l - dl);
            psum += (gi == gj) ? 0.0f : e;
        }
        // reduce across the 16 lanes sharing this row (width-16 groups align
        // with half-warps because tid = ty*16 + tx)
        #pragma unroll
        for (int off = 8; off > 0; off >>= 1)
            psum += __shfl_xor_sync(0xffffffffu, psum, off, 16);
        if (tx == 0) atomicAdd(&g_rowsum[gi], psum);
    }
}

// ---------------------------------------------------------------------------
// Kernel C: loss = mean_i log(rowsum_i)
// ---------------------------------------------------------------------------
__global__ void __launch_bounds__(1024) finalize_kernel(float* __restrict__ out) {
    float s = 0.0f;
    for (int i = threadIdx.x; i < B_DIM; i += 1024) s += logf(g_rowsum[i]);
    #pragma unroll
    for (int off = 16; off > 0; off >>= 1) s += __shfl_xor_sync(0xffffffffu, s, off);
    __shared__ float red[32];
    int wid = threadIdx.x >> 5;
    int lid = threadIdx.x & 31;
    if (lid == 0) red[wid] = s;
    __syncthreads();
    if (threadIdx.x == 0) {
        float tot = 0.0f;
        #pragma unroll
        for (int w = 0; w < 32; w++) tot += red[w];
        out[0] = tot / (float)B_DIM;
    }
}

extern "C" void kernel_launch(void* const* d_in, const int* in_sizes, int n_in,
                              void* d_out, int out_size) {
    const float* t = (const float*)d_in[0];   // text_embeddings  [4096,1024] f32
    const float* m = (const float*)d_in[1];   // image_embeddings [4096,1024] f32
    // d_in[2] = positive_pairs (unused by the loss body)
    float* out = (float*)d_out;

    row_stats_kernel<<<B_DIM, 256>>>(t, m);
    dim3 grid(B_DIM / BN, B_DIM / BM);
    gemm_lse_kernel<<<grid, 256>>>(t, m);
    finalize_kernel<<<1, 1024>>>(out);
}

// round 10
// speedup vs baseline: 4.1098x; 4.1098x over previous
#include <cuda_runtime.h>
#include <cuda_bf16.h>
#include <math.h>
#include <stdint.h>

#define B_DIM 4096
#define D_DIM 1024
#define K2    2048            // [hi | lo] split-K
#define TEMP_INV 20.0f        // 1 / 0.05

#define BM 128
#define BN 128
#define BK 64                 // bf16 per chunk = 128 bytes per row
#define CHUNKS (K2 / BK)      // 32
#define STAGES 3
#define STAGE_BYTES (BM * 128 + BN * 128)   // 16KB A + 16KB B = 32KB
#define SMEM_DYN (STAGES * STAGE_BYTES)     // 96KB

// ---------------- scratch (__device__ globals; no allocs allowed) -----------
__device__ __align__(256) __nv_bfloat16 g_A[B_DIM * K2];   // [hi(t)|lo(t)], 16MB
__device__ __align__(256) __nv_bfloat16 g_Bm[B_DIM * K2];  // [hi(m)|lo(m)], 16MB
__device__ float g_tnorm2[B_DIM];
__device__ float g_mnorm2[B_DIM];
__device__ float g_diaglogit[B_DIM];        // -d_ii / T
__device__ float g_rowsum[B_DIM];

// ---------------- PTX helpers (baseline sm_80+ only; NO tcgen05) ------------
__device__ __forceinline__ uint32_t smem_u32(const void* p) {
    uint32_t a;
    asm("{ .reg .u64 t; cvta.to.shared.u64 t, %1; cvt.u32.u64 %0, t; }" : "=r"(a) : "l"(p));
    return a;
}
__device__ __forceinline__ void cp_async16(uint32_t sdst, const void* gsrc) {
    asm volatile("cp.async.cg.shared.global [%0], [%1], 16;" :: "r"(sdst), "l"(gsrc));
}
#define CP_COMMIT() asm volatile("cp.async.commit_group;" ::: "memory")
#define CP_WAIT(N)  asm volatile("cp.async.wait_group %0;" :: "n"(N) : "memory")

__device__ __forceinline__ void ldsm_x4(uint32_t& r0, uint32_t& r1, uint32_t& r2,
                                        uint32_t& r3, uint32_t addr) {
    asm volatile("ldmatrix.sync.aligned.m8n8.x4.shared.b16 {%0,%1,%2,%3}, [%4];"
                 : "=r"(r0), "=r"(r1), "=r"(r2), "=r"(r3) : "r"(addr));
}
__device__ __forceinline__ void mma16816(float* c, const uint32_t* a,
                                         uint32_t b0, uint32_t b1) {
    asm volatile(
        "mma.sync.aligned.m16n8k16.row.col.f32.bf16.bf16.f32 "
        "{%0,%1,%2,%3}, {%4,%5,%6,%7}, {%8,%9}, {%0,%1,%2,%3};"
        : "+f"(c[0]), "+f"(c[1]), "+f"(c[2]), "+f"(c[3])
        : "r"(a[0]), "r"(a[1]), "r"(a[2]), "r"(a[3]), "r"(b0), "r"(b1));
}

// ---------------------------------------------------------------------------
// Kernel A: bf16 hi/lo split + per-row norms + diag logit + zero rowsum.
// ---------------------------------------------------------------------------
__global__ void __launch_bounds__(256) prep_kernel(const float* __restrict__ t,
                                                   const float* __restrict__ m) {
    int row = blockIdx.x;
    int tid = threadIdx.x;
    const float4 a = reinterpret_cast<const float4*>(t + (size_t)row * D_DIM)[tid];
    const float4 b = reinterpret_cast<const float4*>(m + (size_t)row * D_DIM)[tid];

    float av[4] = {a.x, a.y, a.z, a.w};
    float bv[4] = {b.x, b.y, b.z, b.w};
    __nv_bfloat16 ah[4], al[4], bh[4], bl[4];
    #pragma unroll
    for (int i = 0; i < 4; i++) {
        ah[i] = __float2bfloat16(av[i]);
        al[i] = __float2bfloat16(av[i] - __bfloat162float(ah[i]));
        bh[i] = __float2bfloat16(bv[i]);
        bl[i] = __float2bfloat16(bv[i] - __bfloat162float(bh[i]));
    }
    size_t base = (size_t)row * K2 + tid * 4;
    *reinterpret_cast<uint2*>(&g_A[base])         = *reinterpret_cast<uint2*>(ah);
    *reinterpret_cast<uint2*>(&g_A[base + 1024])  = *reinterpret_cast<uint2*>(al);
    *reinterpret_cast<uint2*>(&g_Bm[base])        = *reinterpret_cast<uint2*>(bh);
    *reinterpret_cast<uint2*>(&g_Bm[base + 1024]) = *reinterpret_cast<uint2*>(bl);

    float st = 0.f, sm = 0.f, sd = 0.f;
    #pragma unroll
    for (int i = 0; i < 4; i++) {
        st = fmaf(av[i], av[i], st);
        sm = fmaf(bv[i], bv[i], sm);
        sd = fmaf(av[i], bv[i], sd);
    }
    #pragma unroll
    for (int off = 16; off > 0; off >>= 1) {
        st += __shfl_xor_sync(0xffffffffu, st, off);
        sm += __shfl_xor_sync(0xffffffffu, sm, off);
        sd += __shfl_xor_sync(0xffffffffu, sd, off);
    }
    __shared__ float red[3][8];
    int wid = tid >> 5, lid = tid & 31;
    if (lid == 0) { red[0][wid] = st; red[1][wid] = sm; red[2][wid] = sd; }
    __syncthreads();
    if (tid == 0) {
        float a0 = 0.f, a1 = 0.f, a2 = 0.f;
        #pragma unroll
        for (int w = 0; w < 8; w++) { a0 += red[0][w]; a1 += red[1][w]; a2 += red[2][w]; }
        g_tnorm2[row] = a0;
        g_mnorm2[row] = a1;
        float d2 = fmaxf(a0 + a1 - 2.0f * a2, 0.0f);
        g_diaglogit[row] = -sqrtf(d2) * TEMP_INV;
        g_rowsum[row] = 0.0f;
    }
}

// ---------------------------------------------------------------------------
// Kernel B: bf16 HMMA GEMM (mma.sync m16n8k16) + fused distance/exp epilogue.
// 128x128 block tile, 8 warps (4x2), warp tile 32x64, 3-stage cp.async.
// ---------------------------------------------------------------------------
__global__ void __launch_bounds__(256) gemm_mma_kernel() {
    extern __shared__ __align__(1024) char dsm[];

    const int tid  = threadIdx.x;
    const int lane = tid & 31;
    const int warp = tid >> 5;
    const int wr   = warp & 3;     // warp row 0..3  (32 rows each)
    const int wc   = warp >> 2;    // warp col 0..1  (64 cols each)
    const int rowBase = blockIdx.y * BM;
    const int colBase = blockIdx.x * BN;

    const uint32_t sbase = smem_u32(dsm);
    const char* gA = reinterpret_cast<const char*>(g_A)  + (size_t)rowBase * (K2 * 2);
    const char* gB = reinterpret_cast<const char*>(g_Bm) + (size_t)colBase * (K2 * 2);

    // ---- per-thread cp.async mapping: 4 iters cover 128 rows x 8 x 16B ----
    // idx = it*256+tid ; r = idx>>3 ; c = idx&7 ; swizzled slot = c ^ (r&7)
    auto load_stage = [&](int chunk, int stage) {
        uint32_t sA = sbase + stage * STAGE_BYTES;
        uint32_t sB = sA + BM * 128;
        #pragma unroll
        for (int it = 0; it < 4; it++) {
            int i2 = it * 256 + tid;
            int r = i2 >> 3, c = i2 & 7;
            uint32_t so = r * 128 + ((c ^ (r & 7)) << 4);
            size_t go = (size_t)r * (K2 * 2) + (size_t)chunk * 128 + c * 16;
            cp_async16(sA + so, gA + go);
            cp_async16(sB + so, gB + go);
        }
        CP_COMMIT();
    };

    // ---- ldmatrix base addresses (ks=0); per-ks address = base ^ (ks<<5) ----
    const int l16 = lane >> 4;          // 0/1 : k-slot within step
    const int lr  = lane & 15;          // row within 16-row tile
    uint32_t aOff[2], bOff[4];
    #pragma unroll
    for (int mi = 0; mi < 2; mi++) {
        int r = wr * 32 + mi * 16 + lr;
        aOff[mi] = r * 128 + ((l16 ^ (r & 7)) << 4);
    }
    #pragma unroll
    for (int p = 0; p < 4; p++) {
        int r = wc * 64 + p * 16 + lr;
        bOff[p] = BM * 128 + r * 128 + ((l16 ^ (r & 7)) << 4);
    }

    float acc[2][8][4];
    #pragma unroll
    for (int mi = 0; mi < 2; mi++)
        #pragma unroll
        for (int ni = 0; ni < 8; ni++)
            #pragma unroll
            for (int q = 0; q < 4; q++) acc[mi][ni][q] = 0.0f;

    load_stage(0, 0);
    load_stage(1, 1);

    for (int k = 0; k < CHUNKS; k++) {
        if (k < CHUNKS - 1) { CP_WAIT(1); } else { CP_WAIT(0); }
        __syncthreads();

        const uint32_t sStage = sbase + (k % STAGES) * STAGE_BYTES;
        #pragma unroll
        for (int ks = 0; ks < 4; ks++) {
            const uint32_t kx = (uint32_t)(ks << 5);
            uint32_t a[2][4], b[4][4];
            #pragma unroll
            for (int mi = 0; mi < 2; mi++)
                ldsm_x4(a[mi][0], a[mi][1], a[mi][2], a[mi][3],
                        sStage + (aOff[mi] ^ kx));
            #pragma unroll
            for (int p = 0; p < 4; p++)
                ldsm_x4(b[p][0], b[p][1], b[p][2], b[p][3],
                        sStage + (bOff[p] ^ kx));
            #pragma unroll
            for (int mi = 0; mi < 2; mi++)
                #pragma unroll
                for (int p = 0; p < 4; p++) {
                    mma16816(acc[mi][2 * p + 0], a[mi], b[p][0], b[p][2]);
                    mma16816(acc[mi][2 * p + 1], a[mi], b[p][1], b[p][3]);
                }
        }

        if (k + 2 < CHUNKS) load_stage(k + 2, (k + 2) % STAGES);
    }

    // -------------------- fused epilogue --------------------
    __syncthreads();                     // all warps done with smem stages
    float* s_mn = reinterpret_cast<float*>(dsm);
    if (tid < BN) s_mn[tid] = g_mnorm2[colBase + tid];
    __syncthreads();

    const int rloc = wr * 32 + (lane >> 2);
    #pragma unroll
    for (int mi = 0; mi < 2; mi++) {
        #pragma unroll
        for (int h = 0; h < 2; h++) {
            const int gi = rowBase + rloc + mi * 16 + h * 8;
            const float tn = g_tnorm2[gi];
            const float dl = g_diaglogit[gi];
            float ps = 0.0f;
            #pragma unroll
            for (int ni = 0; ni < 8; ni++) {
                const int cl = wc * 64 + ni * 8 + (lane & 3) * 2;
                #pragma unroll
                for (int q = 0; q < 2; q++) {
                    const int gj = colBase + cl + q;
                    float dot = acc[mi][ni][h * 2 + q];
                    float d2 = fmaxf(fmaf(-2.0f, dot, tn + s_mn[cl + q]), 1e-12f);
                    float d = d2 * __frsqrt_rn(d2);               // sqrt(d2)
                    float e = __expf(fmaf(-TEMP_INV, d, -dl));    // exp(l - diag)
                    ps += (gi == gj) ? 0.0f : e;
                }
            }
            ps += __shfl_xor_sync(0xffffffffu, ps, 1);
            ps += __shfl_xor_sync(0xffffffffu, ps, 2);
            if ((lane & 3) == 0) atomicAdd(&g_rowsum[gi], ps);
        }
    }
}

// ---------------------------------------------------------------------------
// Kernel C: loss = mean_i log(rowsum_i)
// ---------------------------------------------------------------------------
__global__ void __launch_bounds__(1024) finalize_kernel(float* __restrict__ out) {
    float s = 0.0f;
    for (int i = threadIdx.x; i < B_DIM; i += 1024) s += logf(g_rowsum[i]);
    #pragma unroll
    for (int off = 16; off > 0; off >>= 1) s += __shfl_xor_sync(0xffffffffu, s, off);
    __shared__ float red[32];
    int wid = threadIdx.x >> 5, lid = threadIdx.x & 31;
    if (lid == 0) red[wid] = s;
    __syncthreads();
    if (threadIdx.x == 0) {
        float tot = 0.0f;
        #pragma unroll
        for (int w = 0; w < 32; w++) tot += red[w];
        out[0] = tot / (float)B_DIM;
    }
}

extern "C" void kernel_launch(void* const* d_in, const int* in_sizes, int n_in,
                              void* d_out, int out_size) {
    const float* t = (const float*)d_in[0];
    const float* m = (const float*)d_in[1];
    float* out = (float*)d_out;

    cudaFuncSetAttribute(gemm_mma_kernel,
                         cudaFuncAttributeMaxDynamicSharedMemorySize, SMEM_DYN);

    prep_kernel<<<B_DIM, 256>>>(t, m);
    dim3 grid(B_DIM / BN, B_DIM / BM);   // (32, 32)
    gemm_mma_kernel<<<grid, 256, SMEM_DYN>>>();
    finalize_kernel<<<1, 1024>>>(out);
}

// round 13
// speedup vs baseline: 6.9486x; 1.6907x over previous
#include <cuda_runtime.h>
#include <cuda_bf16.h>
#include <math.h>
#include <stdint.h>

#define B_DIM 4096
#define D_DIM 1024
#define K_TOT 1024            // pure bf16-hi GEMM (cross terms dominate error either way)
#define TEMP_INV 20.0f        // 1 / 0.05

#define BM 128
#define BN 128
#define BK 64                 // bf16 per chunk = 128 bytes per row
#define CHUNKS (K_TOT / BK)   // 16
#define STAGES 3
#define STAGE_BYTES (BM * 128 + BN * 128)   // 16KB A + 16KB B = 32KB
#define SMEM_DYN (STAGES * STAGE_BYTES)     // 96KB

// ---------------- scratch (__device__ globals; no allocs allowed) -----------
__device__ __align__(256) __nv_bfloat16 g_A[B_DIM * K_TOT];   // hi(t), 8MB
__device__ __align__(256) __nv_bfloat16 g_Bm[B_DIM * K_TOT];  // hi(m), 8MB
__device__ float g_tnorm2[B_DIM];
__device__ float g_mnorm2[B_DIM];
__device__ float g_diaglogit[B_DIM];        // -d_ii / T
__device__ float g_rowsum[B_DIM];

// ---------------- PTX helpers (baseline sm_80+ only; NO tcgen05) ------------
__device__ __forceinline__ uint32_t smem_u32(const void* p) {
    uint32_t a;
    asm("{ .reg .u64 t; cvta.to.shared.u64 t, %1; cvt.u32.u64 %0, t; }" : "=r"(a) : "l"(p));
    return a;
}
__device__ __forceinline__ void cp_async16(uint32_t sdst, const void* gsrc) {
    asm volatile("cp.async.cg.shared.global [%0], [%1], 16;" :: "r"(sdst), "l"(gsrc));
}
#define CP_COMMIT() asm volatile("cp.async.commit_group;" ::: "memory")
#define CP_WAIT(N)  asm volatile("cp.async.wait_group %0;" :: "n"(N) : "memory")

__device__ __forceinline__ void ldsm_x4(uint32_t& r0, uint32_t& r1, uint32_t& r2,
                                        uint32_t& r3, uint32_t addr) {
    asm volatile("ldmatrix.sync.aligned.m8n8.x4.shared.b16 {%0,%1,%2,%3}, [%4];"
                 : "=r"(r0), "=r"(r1), "=r"(r2), "=r"(r3) : "r"(addr));
}
__device__ __forceinline__ void mma16816(float* c, const uint32_t* a,
                                         uint32_t b0, uint32_t b1) {
    asm volatile(
        "mma.sync.aligned.m16n8k16.row.col.f32.bf16.bf16.f32 "
        "{%0,%1,%2,%3}, {%4,%5,%6,%7}, {%8,%9}, {%0,%1,%2,%3};"
        : "+f"(c[0]), "+f"(c[1]), "+f"(c[2]), "+f"(c[3])
        : "r"(a[0]), "r"(a[1]), "r"(a[2]), "r"(a[3]), "r"(b0), "r"(b1));
}

// ---------------------------------------------------------------------------
// Kernel A: bf16 round + per-row norms (exact fp32) + diag logit + zero rowsum.
// ---------------------------------------------------------------------------
__global__ void __launch_bounds__(256) prep_kernel(const float* __restrict__ t,
                                                   const float* __restrict__ m) {
    int row = blockIdx.x;
    int tid = threadIdx.x;
    const float4 a = reinterpret_cast<const float4*>(t + (size_t)row * D_DIM)[tid];
    const float4 b = reinterpret_cast<const float4*>(m + (size_t)row * D_DIM)[tid];

    float av[4] = {a.x, a.y, a.z, a.w};
    float bv[4] = {b.x, b.y, b.z, b.w};
    __nv_bfloat16 ah[4], bh[4];
    #pragma unroll
    for (int i = 0; i < 4; i++) {
        ah[i] = __float2bfloat16(av[i]);
        bh[i] = __float2bfloat16(bv[i]);
    }
    size_t base = (size_t)row * K_TOT + tid * 4;
    *reinterpret_cast<uint2*>(&g_A[base])  = *reinterpret_cast<uint2*>(ah);
    *reinterpret_cast<uint2*>(&g_Bm[base]) = *reinterpret_cast<uint2*>(bh);

    float st = 0.f, sm = 0.f, sd = 0.f;
    #pragma unroll
    for (int i = 0; i < 4; i++) {
        st = fmaf(av[i], av[i], st);
        sm = fmaf(bv[i], bv[i], sm);
        sd = fmaf(av[i], bv[i], sd);
    }
    #pragma unroll
    for (int off = 16; off > 0; off >>= 1) {
        st += __shfl_xor_sync(0xffffffffu, st, off);
        sm += __shfl_xor_sync(0xffffffffu, sm, off);
        sd += __shfl_xor_sync(0xffffffffu, sd, off);
    }
    __shared__ float red[3][8];
    int wid = tid >> 5, lid = tid & 31;
    if (lid == 0) { red[0][wid] = st; red[1][wid] = sm; red[2][wid] = sd; }
    __syncthreads();
    if (tid == 0) {
        float a0 = 0.f, a1 = 0.f, a2 = 0.f;
        #pragma unroll
        for (int w = 0; w < 8; w++) { a0 += red[0][w]; a1 += red[1][w]; a2 += red[2][w]; }
        g_tnorm2[row] = a0;
        g_mnorm2[row] = a1;
        float d2 = fmaxf(a0 + a1 - 2.0f * a2, 0.0f);
        g_diaglogit[row] = -sqrtf(d2) * TEMP_INV;
        g_rowsum[row] = 0.0f;
    }
}

// ---------------------------------------------------------------------------
// Kernel B: bf16 HMMA GEMM (mma.sync m16n8k16, K=1024) + fused dist/exp epi.
// 128x128 block tile, 8 warps (4x2), warp tile 32x64, 3-stage cp.async.
// ---------------------------------------------------------------------------
__global__ void __launch_bounds__(256) gemm_mma_kernel() {
    extern __shared__ __align__(1024) char dsm[];

    const int tid  = threadIdx.x;
    const int lane = tid & 31;
    const int warp = tid >> 5;
    const int wr   = warp & 3;     // warp row 0..3  (32 rows each)
    const int wc   = warp >> 2;    // warp col 0..1  (64 cols each)
    const int rowBase = blockIdx.y * BM;
    const int colBase = blockIdx.x * BN;

    const uint32_t sbase = smem_u32(dsm);
    const char* gA = reinterpret_cast<const char*>(g_A)  + (size_t)rowBase * (K_TOT * 2);
    const char* gB = reinterpret_cast<const char*>(g_Bm) + (size_t)colBase * (K_TOT * 2);

    // ---- per-thread cp.async mapping: 4 iters cover 128 rows x 8 x 16B ----
    auto load_stage = [&](int chunk, int stage) {
        uint32_t sA = sbase + stage * STAGE_BYTES;
        uint32_t sB = sA + BM * 128;
        #pragma unroll
        for (int it = 0; it < 4; it++) {
            int i2 = it * 256 + tid;
            int r = i2 >> 3, c = i2 & 7;
            uint32_t so = r * 128 + ((c ^ (r & 7)) << 4);
            size_t go = (size_t)r * (K_TOT * 2) + (size_t)chunk * 128 + c * 16;
            cp_async16(sA + so, gA + go);
            cp_async16(sB + so, gB + go);
        }
        CP_COMMIT();
    };

    // ---- ldmatrix base addresses (ks=0); per-ks address = base ^ (ks<<5) ----
    const int l16 = lane >> 4;
    const int lr  = lane & 15;
    uint32_t aOff[2], bOff[4];
    #pragma unroll
    for (int mi = 0; mi < 2; mi++) {
        int r = wr * 32 + mi * 16 + lr;
        aOff[mi] = r * 128 + ((l16 ^ (r & 7)) << 4);
    }
    #pragma unroll
    for (int p = 0; p < 4; p++) {
        int r = wc * 64 + p * 16 + lr;
        bOff[p] = BM * 128 + r * 128 + ((l16 ^ (r & 7)) << 4);
    }

    float acc[2][8][4];
    #pragma unroll
    for (int mi = 0; mi < 2; mi++)
        #pragma unroll
        for (int ni = 0; ni < 8; ni++)
            #pragma unroll
            for (int q = 0; q < 4; q++) acc[mi][ni][q] = 0.0f;

    load_stage(0, 0);
    load_stage(1, 1);

    for (int k = 0; k < CHUNKS; k++) {
        if (k < CHUNKS - 1) { CP_WAIT(1); } else { CP_WAIT(0); }
        __syncthreads();

        const uint32_t sStage = sbase + (k % STAGES) * STAGE_BYTES;
        #pragma unroll
        for (int ks = 0; ks < 4; ks++) {
            const uint32_t kx = (uint32_t)(ks << 5);
            uint32_t a[2][4], b[4][4];
            #pragma unroll
            for (int mi = 0; mi < 2; mi++)
                ldsm_x4(a[mi][0], a[mi][1], a[mi][2], a[mi][3],
                        sStage + (aOff[mi] ^ kx));
            #pragma unroll
            for (int p = 0; p < 4; p++)
                ldsm_x4(b[p][0], b[p][1], b[p][2], b[p][3],
                        sStage + (bOff[p] ^ kx));
            #pragma unroll
            for (int mi = 0; mi < 2; mi++)
                #pragma unroll
                for (int p = 0; p < 4; p++) {
                    mma16816(acc[mi][2 * p + 0], a[mi], b[p][0], b[p][2]);
                    mma16816(acc[mi][2 * p + 1], a[mi], b[p][1], b[p][3]);
                }
        }

        if (k + 2 < CHUNKS) load_stage(k + 2, (k + 2) % STAGES);
    }

    // -------------------- fused epilogue --------------------
    __syncthreads();
    float* s_mn = reinterpret_cast<float*>(dsm);
    if (tid < BN) s_mn[tid] = g_mnorm2[colBase + tid];
    __syncthreads();

    const int rloc = wr * 32 + (lane >> 2);
    #pragma unroll
    for (int mi = 0; mi < 2; mi++) {
        #pragma unroll
        for (int h = 0; h < 2; h++) {
            const int gi = rowBase + rloc + mi * 16 + h * 8;
            const float tn = g_tnorm2[gi];
            const float dl = g_diaglogit[gi];
            float ps = 0.0f;
            #pragma unroll
            for (int ni = 0; ni < 8; ni++) {
                const int cl = wc * 64 + ni * 8 + (lane & 3) * 2;
                #pragma unroll
                for (int q = 0; q < 2; q++) {
                    const int gj = colBase + cl + q;
                    float dot = acc[mi][ni][h * 2 + q];
                    float d2 = fmaxf(fmaf(-2.0f, dot, tn + s_mn[cl + q]), 1e-12f);
                    float d = d2 * __frsqrt_rn(d2);               // sqrt(d2)
                    float e = __expf(fmaf(-TEMP_INV, d, -dl));    // exp(l - diag)
                    ps += (gi == gj) ? 0.0f : e;
                }
            }
            ps += __shfl_xor_sync(0xffffffffu, ps, 1);
            ps += __shfl_xor_sync(0xffffffffu, ps, 2);
            if ((lane & 3) == 0) atomicAdd(&g_rowsum[gi], ps);
        }
    }
}

// ---------------------------------------------------------------------------
// Kernel C: loss = mean_i log(rowsum_i)
// ---------------------------------------------------------------------------
__global__ void __launch_bounds__(1024) finalize_kernel(float* __restrict__ out) {
    float s = 0.0f;
    for (int i = threadIdx.x; i < B_DIM; i += 1024) s += logf(g_rowsum[i]);
    #pragma unroll
    for (int off = 16; off > 0; off >>= 1) s += __shfl_xor_sync(0xffffffffu, s, off);
    __shared__ float red[32];
    int wid = threadIdx.x >> 5, lid = threadIdx.x & 31;
    if (lid == 0) red[wid] = s;
    __syncthreads();
    if (threadIdx.x == 0) {
        float tot = 0.0f;
        #pragma unroll
        for (int w = 0; w < 32; w++) tot += red[w];
        out[0] = tot / (float)B_DIM;
    }
}

extern "C" void kernel_launch(void* const* d_in, const int* in_sizes, int n_in,
                              void* d_out, int out_size) {
    const float* t = (const float*)d_in[0];
    const float* m = (const float*)d_in[1];
    float* out = (float*)d_out;

    cudaFuncSetAttribute(gemm_mma_kernel,
                         cudaFuncAttributeMaxDynamicSharedMemorySize, SMEM_DYN);

    prep_kernel<<<B_DIM, 256>>>(t, m);
    dim3 grid(B_DIM / BN, B_DIM / BM);   // (32, 32)
    gemm_mma_kernel<<<grid, 256, SMEM_DYN>>>();
    finalize_kernel<<<1, 1024>>>(out);
}